// round 1
// baseline (speedup 1.0000x reference)
#include <cuda_runtime.h>
#include <math.h>

#define MAXN 8192
#define THREADS 128
#define QPT 4
#define QBLK (THREADS * QPT)   // 512 queries per block
#define SLAB 512               // DB points per block (8 KB smem)

// Scratch (allocation-free rule): packed points + running min keys.
// float4 = (x, y, z, sigma). Key = (dist2_bits << 32) | sigma_bits.
__device__ float4 g_ref4[MAXN];
__device__ float4 g_src4[MAXN];
__device__ unsigned long long g_fwd[MAXN];
__device__ unsigned long long g_bwd[MAXN];

__global__ void init_kernel(const float* __restrict__ ref,
                            const float* __restrict__ src,
                            const float* __restrict__ T,
                            const float* __restrict__ rsig,
                            const float* __restrict__ ssig,
                            int n, int m) {
    int i = blockIdx.x * blockDim.x + threadIdx.x;
    if (i < n) {
        g_ref4[i] = make_float4(ref[3*i], ref[3*i+1], ref[3*i+2], rsig[i]);
        g_fwd[i] = ~0ULL;
    }
    if (i < m) {
        float x = src[3*i], y = src[3*i+1], z = src[3*i+2];
        // kpts2 = src @ R^T + t ; R = T[:3,:3], t = T[:3,3] (row-major 4x4)
        float X = T[0]*x + T[1]*y + T[2]*z  + T[3];
        float Y = T[4]*x + T[5]*y + T[6]*z  + T[7];
        float Z = T[8]*x + T[9]*y + T[10]*z + T[11];
        g_src4[i] = make_float4(X, Y, Z, ssig[i]);
        g_bwd[i] = ~0ULL;
    }
}

// dir == 0: queries = ref, DB = src (forward).  dir == 1: swapped (backward).
// Each block: QBLK queries x one SLAB of the DB; partial min merged via u64 atomicMin.
__global__ void __launch_bounds__(THREADS) nn_kernel(int dir, int nA, int nB) {
    const float4* __restrict__ A = dir ? g_src4 : g_ref4;
    const float4* __restrict__ B = dir ? g_ref4 : g_src4;
    unsigned long long* __restrict__ keys = dir ? g_bwd : g_fwd;

    __shared__ float4 sB[SLAB];
    int tid = threadIdx.x;
    int jbase = blockIdx.y * SLAB;

    // Cooperative slab load (pad OOB with +huge so it never wins the min).
    for (int j = tid; j < SLAB; j += THREADS) {
        int gj = jbase + j;
        sB[j] = (gj < nB) ? B[gj] : make_float4(1e30f, 1e30f, 1e30f, 1.0f);
    }

    // 4 independent query chains per thread (hides FSETP->SEL dependency).
    float ax[QPT], ay[QPT], az[QPT], bd[QPT], bs[QPT];
    int q0 = blockIdx.x * QBLK + tid;
#pragma unroll
    for (int q = 0; q < QPT; q++) {
        int qi = q0 + q * THREADS;
        float4 a = (qi < nA) ? A[qi] : make_float4(0.f, 0.f, 0.f, 0.f);
        ax[q] = a.x; ay[q] = a.y; az[q] = a.z;
        bd[q] = 3.4e38f; bs[q] = 1.0f;
    }
    __syncthreads();

#pragma unroll 4
    for (int j = 0; j < SLAB; j++) {
        float4 b = sB[j];   // broadcast LDS.128, conflict-free
#pragma unroll
        for (int q = 0; q < QPT; q++) {
            float dx = ax[q] - b.x;
            float dy = ay[q] - b.y;
            float dz = az[q] - b.z;
            float d  = fmaf(dx, dx, fmaf(dy, dy, dz * dz));
            if (d < bd[q]) { bd[q] = d; bs[q] = b.w; }
        }
    }

#pragma unroll
    for (int q = 0; q < QPT; q++) {
        int qi = q0 + q * THREADS;
        if (qi < nA) {
            unsigned long long key =
                (((unsigned long long)__float_as_uint(bd[q])) << 32) |
                (unsigned long long)__float_as_uint(bs[q]);
            atomicMin(&keys[qi], key);
        }
    }
}

__global__ void reduce_kernel(float* __restrict__ out, int n, int m) {
    __shared__ float ssum[256];
    int tid = threadIdx.x;
    float inv_n = 1.0f / (float)n;
    float inv_m = 1.0f / (float)m;
    float acc = 0.0f;
    for (int i = tid; i < n; i += 256) {
        unsigned long long k = g_fwd[i];
        float d   = sqrtf(__uint_as_float((unsigned)(k >> 32)));
        float sig = 0.5f * (g_ref4[i].w + __uint_as_float((unsigned)k));
        acc += (logf(sig) + d / sig) * inv_n;
    }
    for (int j = tid; j < m; j += 256) {
        unsigned long long k = g_bwd[j];
        float d   = sqrtf(__uint_as_float((unsigned)(k >> 32)));
        float sig = 0.5f * (g_src4[j].w + __uint_as_float((unsigned)k));
        acc += (logf(sig) + d / sig) * inv_m;
    }
    ssum[tid] = acc;
    __syncthreads();
    for (int s = 128; s > 0; s >>= 1) {
        if (tid < s) ssum[tid] += ssum[tid + s];
        __syncthreads();
    }
    if (tid == 0) out[0] = ssum[0];
}

extern "C" void kernel_launch(void* const* d_in, const int* in_sizes, int n_in,
                              void* d_out, int out_size) {
    const float* ref  = (const float*)d_in[0];   // (N,3)
    const float* src  = (const float*)d_in[1];   // (M,3)
    const float* T    = (const float*)d_in[2];   // (4,4)
    const float* rsig = (const float*)d_in[3];   // (N,)
    const float* ssig = (const float*)d_in[4];   // (M,)
    int n = in_sizes[3];
    int m = in_sizes[4];

    int nm = n > m ? n : m;
    init_kernel<<<(nm + 255) / 256, 256>>>(ref, src, T, rsig, ssig, n, m);

    // forward: ref queries (n) vs src DB (m)
    dim3 gf((n + QBLK - 1) / QBLK, (m + SLAB - 1) / SLAB);
    nn_kernel<<<gf, THREADS>>>(0, n, m);
    // backward: src queries (m) vs ref DB (n)
    dim3 gb((m + QBLK - 1) / QBLK, (n + SLAB - 1) / SLAB);
    nn_kernel<<<gb, THREADS>>>(1, m, n);

    reduce_kernel<<<1, 256>>>((float*)d_out, n, m);
}

// round 2
// speedup vs baseline: 1.6985x; 1.6985x over previous
#include <cuda_runtime.h>
#include <math.h>

#define MAXN 8192
#define THREADS 128
#define QPT 4
#define QBLK (THREADS * QPT)   // 512 queries per block
#define SLAB 512               // DB points per slab
#define RBLK 256               // reduce stage-1 block size
#define NPART 64               // partial sums (32 fwd + 32 bwd)

// Scratch (allocation-free rule).
__device__ float4 g_ref4[MAXN];              // (x,y,z,sigma)
__device__ float4 g_src4[MAXN];              // transformed (x,y,z,sigma)
__device__ unsigned long long g_fwd[MAXN];   // (dist2_bits<<32)|sigma_bits
__device__ unsigned long long g_bwd[MAXN];
__device__ float g_part[NPART];

__global__ void init_kernel(const float* __restrict__ ref,
                            const float* __restrict__ src,
                            const float* __restrict__ T,
                            const float* __restrict__ rsig,
                            const float* __restrict__ ssig,
                            int n, int m) {
    int i = blockIdx.x * blockDim.x + threadIdx.x;
    if (i < n) {
        g_ref4[i] = make_float4(ref[3*i], ref[3*i+1], ref[3*i+2], rsig[i]);
        g_fwd[i] = ~0ULL;
    }
    if (i < m) {
        float x = src[3*i], y = src[3*i+1], z = src[3*i+2];
        float X = T[0]*x + T[1]*y + T[2]*z  + T[3];
        float Y = T[4]*x + T[5]*y + T[6]*z  + T[7];
        float Z = T[8]*x + T[9]*y + T[10]*z + T[11];
        g_src4[i] = make_float4(X, Y, Z, ssig[i]);
        g_bwd[i] = ~0ULL;
    }
}

// dir==0: queries=ref, DB=src.  dir==1: swapped.
__global__ void __launch_bounds__(THREADS) nn_kernel(int dir, int nA, int nB) {
    const float4* __restrict__ A = dir ? g_src4 : g_ref4;
    const float4* __restrict__ B = dir ? g_ref4 : g_src4;
    unsigned long long* __restrict__ keys = dir ? g_bwd : g_fwd;

    __shared__ float4 sBt[SLAB];   // (-2x, -2y, -2z, |b|^2) — hot inner-loop form
    __shared__ float4 sBo[SLAB];   // (x, y, z, sigma)       — epilogue form
    int tid = threadIdx.x;
    int jbase = blockIdx.y * SLAB;

    for (int j = tid; j < SLAB; j += THREADS) {
        int gj = jbase + j;
        float4 b = (gj < nB) ? B[gj] : make_float4(1e15f, 1e15f, 1e15f, 1.0f);
        sBo[j] = b;
        float b2 = fmaf(b.x, b.x, fmaf(b.y, b.y, b.z * b.z));
        sBt[j] = make_float4(-2.0f * b.x, -2.0f * b.y, -2.0f * b.z, b2);
    }

    // 4 independent query chains per thread.
    float ax[QPT], ay[QPT], az[QPT], bd[QPT];
    int   bj[QPT];
    int q0 = blockIdx.x * QBLK + tid;
#pragma unroll
    for (int q = 0; q < QPT; q++) {
        int qi = q0 + q * THREADS;
        float4 a = (qi < nA) ? A[qi] : make_float4(0.f, 0.f, 0.f, 0.f);
        ax[q] = a.x; ay[q] = a.y; az[q] = a.z;
        bd[q] = 3.4e38f; bj[q] = 0;
    }
    __syncthreads();

    // d' = |b|^2 - 2 a.b  (query-constant |a|^2 dropped: argmin-preserving)
#pragma unroll 4
    for (int j = 0; j < SLAB; j++) {
        float4 b = sBt[j];   // broadcast LDS.128
#pragma unroll
        for (int q = 0; q < QPT; q++) {
            float d = fmaf(ax[q], b.x, fmaf(ay[q], b.y, fmaf(az[q], b.z, b.w)));
            if (d < bd[q]) { bd[q] = d; bj[q] = j; }
        }
    }

    // Epilogue: exact non-negative dist^2 for the winner, pack with its sigma.
#pragma unroll
    for (int q = 0; q < QPT; q++) {
        int qi = q0 + q * THREADS;
        if (qi < nA) {
            float4 b = sBo[bj[q]];
            float dx = ax[q] - b.x, dy = ay[q] - b.y, dz = az[q] - b.z;
            float d2 = fmaf(dx, dx, fmaf(dy, dy, dz * dz));
            unsigned long long key =
                (((unsigned long long)__float_as_uint(d2)) << 32) |
                (unsigned long long)__float_as_uint(b.w);
            atomicMin(&keys[qi], key);
        }
    }
}

// Stage 1: 64 blocks, each reduces 256 entries to one partial sum (deterministic).
__global__ void __launch_bounds__(RBLK) reduce1_kernel(int n, int m) {
    __shared__ float ssum[RBLK];
    int tid = threadIdx.x;
    int b = blockIdx.x;
    float acc = 0.0f;
    if (b < NPART / 2) {
        int i = b * RBLK + tid;
        if (i < n) {
            unsigned long long k = g_fwd[i];
            float d   = sqrtf(__uint_as_float((unsigned)(k >> 32)));
            float sig = 0.5f * (g_ref4[i].w + __uint_as_float((unsigned)k));
            acc = (__logf(sig) + __fdividef(d, sig)) * (1.0f / (float)n);
        }
    } else {
        int i = (b - NPART / 2) * RBLK + tid;
        if (i < m) {
            unsigned long long k = g_bwd[i];
            float d   = sqrtf(__uint_as_float((unsigned)(k >> 32)));
            float sig = 0.5f * (g_src4[i].w + __uint_as_float((unsigned)k));
            acc = (__logf(sig) + __fdividef(d, sig)) * (1.0f / (float)m);
        }
    }
    ssum[tid] = acc;
    __syncthreads();
    for (int s = RBLK / 2; s >= 32; s >>= 1) {
        if (tid < s) ssum[tid] += ssum[tid + s];
        __syncthreads();
    }
    if (tid < 32) {
        float v = ssum[tid];
#pragma unroll
        for (int o = 16; o > 0; o >>= 1)
            v += __shfl_xor_sync(0xFFFFFFFF, v, o);
        if (tid == 0) g_part[b] = v;
    }
}

__global__ void reduce2_kernel(float* __restrict__ out) {
    int tid = threadIdx.x;
    float v = g_part[tid];   // NPART == 64 == blockDim
    __shared__ float s32[2];
#pragma unroll
    for (int o = 16; o > 0; o >>= 1)
        v += __shfl_xor_sync(0xFFFFFFFF, v, o);
    if ((tid & 31) == 0) s32[tid >> 5] = v;
    __syncthreads();
    if (tid == 0) out[0] = s32[0] + s32[1];
}

extern "C" void kernel_launch(void* const* d_in, const int* in_sizes, int n_in,
                              void* d_out, int out_size) {
    const float* ref  = (const float*)d_in[0];
    const float* src  = (const float*)d_in[1];
    const float* T    = (const float*)d_in[2];
    const float* rsig = (const float*)d_in[3];
    const float* ssig = (const float*)d_in[4];
    int n = in_sizes[3];
    int m = in_sizes[4];

    int nm = n > m ? n : m;
    init_kernel<<<(nm + 255) / 256, 256>>>(ref, src, T, rsig, ssig, n, m);

    dim3 gf((n + QBLK - 1) / QBLK, (m + SLAB - 1) / SLAB);
    nn_kernel<<<gf, THREADS>>>(0, n, m);
    dim3 gb((m + QBLK - 1) / QBLK, (n + SLAB - 1) / SLAB);
    nn_kernel<<<gb, THREADS>>>(1, m, n);

    reduce1_kernel<<<NPART, RBLK>>>(n, m);
    reduce2_kernel<<<1, NPART>>>((float*)d_out);
}